// round 1
// baseline (speedup 1.0000x reference)
#include <cuda_runtime.h>

// LocalBinaryLayer: LBP (radius=1, P=8) + 8-bin histogram (range 0..255, density).
// Critical reduction: bin = code >> 5 == top 3 LBP bits (i=5,6,7) only.
//   i=5: (dy,dx)=( +s, -s)  bilinear over {(0,-1),(0,0),(1,-1),(1,0)}
//   i=6: (dy,dx)=( +1,  0)  exact neighbor (1,0)
//   i=7: (dy,dx)=( +s, +s)  bilinear over {(0,0),(0,1),(1,0),(1,1)}
// with s = sqrt(2)/2. Zero padding outside the image.

#define IMG_W 512
#define IMG_H 512
#define NCH   96          // 32 batch * 3 channels
#define NBINS 8
#define BLOCK 128         // threads; each owns 4 columns -> 512 wide
#define ROWS  32          // rows per block tile
#define TILES (IMG_H / ROWS)   // 16

__device__ unsigned int g_counts[NCH * NBINS];

// bilinear weights (float64 products rounded to f32, matching reference)
#define W_EDGE 0.20710678118654752f
#define W_CENT 0.08578643762690495f
#define W_DIAG 0.5f

struct Row6 { float L, v0, v1, v2, v3, R; };

__device__ __forceinline__ Row6 load_row(const float* __restrict__ img,
                                         int y, int t, int lane) {
    Row6 r;
    if (y < IMG_H) {   // uniform per block -> shuffles safe
        const float4 v = *reinterpret_cast<const float4*>(img + (size_t)y * IMG_W + 4 * t);
        r.v0 = v.x; r.v1 = v.y; r.v2 = v.z; r.v3 = v.w;
        r.L = __shfl_up_sync(0xffffffffu, v.w, 1);
        r.R = __shfl_down_sync(0xffffffffu, v.x, 1);
        if (lane == 0)
            r.L = (t == 0) ? 0.0f : __ldg(img + (size_t)y * IMG_W + 4 * t - 1);
        if (lane == 31)
            r.R = (t == BLOCK - 1) ? 0.0f : __ldg(img + (size_t)y * IMG_W + 4 * t + 4);
    } else {
        r.L = r.v0 = r.v1 = r.v2 = r.v3 = r.R = 0.0f;
    }
    return r;
}

__global__ void __launch_bounds__(BLOCK)
lbp_hist_kernel(const float* __restrict__ x) {
    __shared__ unsigned int s_hist[NBINS];
    const int t    = threadIdx.x;
    const int lane = t & 31;
    const int ch   = blockIdx.y;
    const int y0   = blockIdx.x * ROWS;
    const float* __restrict__ img = x + (size_t)ch * IMG_H * IMG_W;

    if (t < NBINS) s_hist[t] = 0u;
    __syncthreads();

    unsigned long long packed = 0ull;   // 8 bins x 8-bit counters (max 128/thread)

    Row6 cur = load_row(img, y0, t, lane);

    #pragma unroll 4
    for (int r = 0; r < ROWS; ++r) {
        Row6 nxt = load_row(img, y0 + r + 1, t, lane);

        // process pixel with (curL, c, curR) / (nxtL, nc, nxtR)
        #define PX(a, c, e, na, nc, ne) do {                                   \
            float nb5 = W_EDGE*(a) + W_CENT*(c) + W_DIAG*(na) + W_EDGE*(nc);   \
            float nb7 = W_CENT*(c) + W_EDGE*(e) + W_EDGE*(nc) + W_DIAG*(ne);   \
            int bin = ((nb7 >= (c)) ? 4 : 0)                                   \
                    | (((nc) >= (c)) ? 2 : 0)                                  \
                    | ((nb5 >= (c)) ? 1 : 0);                                  \
            packed += 1ull << (bin << 3);                                      \
        } while (0)

        PX(cur.L,  cur.v0, cur.v1, nxt.L,  nxt.v0, nxt.v1);
        PX(cur.v0, cur.v1, cur.v2, nxt.v0, nxt.v1, nxt.v2);
        PX(cur.v1, cur.v2, cur.v3, nxt.v1, nxt.v2, nxt.v3);
        PX(cur.v2, cur.v3, cur.R,  nxt.v2, nxt.v3, nxt.R);
        #undef PX

        cur = nxt;
    }

    // unpack + warp reduce + block accumulate
    #pragma unroll
    for (int b = 0; b < NBINS; ++b) {
        unsigned int c = (unsigned int)((packed >> (b * 8)) & 0xFFull);
        c = __reduce_add_sync(0xffffffffu, c);
        if (lane == 0) atomicAdd(&s_hist[b], c);
    }
    __syncthreads();
    if (t < NBINS) atomicAdd(&g_counts[ch * NBINS + t], s_hist[t]);
}

__global__ void zero_counts_kernel() {
    int i = blockIdx.x * blockDim.x + threadIdx.x;
    if (i < NCH * NBINS) g_counts[i] = 0u;
}

__global__ void finalize_kernel(float* __restrict__ out) {
    int i = blockIdx.x * blockDim.x + threadIdx.x;
    if (i < NCH * NBINS)
        out[i] = (float)g_counts[i] / 8355840.0f;  // H*W*width = 262144*31.875
}

extern "C" void kernel_launch(void* const* d_in, const int* in_sizes, int n_in,
                              void* d_out, int out_size) {
    const float* x = (const float*)d_in[0];
    float* out = (float*)d_out;

    zero_counts_kernel<<<1, NCH * NBINS>>>();
    dim3 grid(TILES, NCH);
    lbp_hist_kernel<<<grid, BLOCK>>>(x);
    finalize_kernel<<<1, NCH * NBINS>>>(out);
}

// round 3
// speedup vs baseline: 1.0811x; 1.0811x over previous
#include <cuda_runtime.h>

// LocalBinaryLayer: LBP (radius=1, P=8) + 8-bin histogram (range 0..255, density).
// bin = code >> 5 == top 3 LBP bits (i=5,6,7) only:
//   i=5: (dy,dx)=(+s,-s)  bilinear over {(0,-1),(0,0),(1,-1),(1,0)}
//   i=6: (dy,dx)=(+1, 0)  exact neighbor (1,0)
//   i=7: (dy,dx)=(+s,+s)  bilinear over {(0,0),(0,1),(1,0),(1,1)}
// s = sqrt(2)/2, zero padding. Single kernel: per-block packed-register
// histograms -> global atomics -> last block normalizes & self-resets state.

#define IMG_W 512
#define IMG_H 512
#define NCH   96          // 32 batch * 3 channels
#define NBINS 8
#define BLOCK 128         // threads; each owns 4 columns -> 512 wide
#define ROWS  32          // rows per block tile (128 px/thread -> fits u8 fields)
#define TILES (IMG_H / ROWS)   // 16
#define NBLOCKS (TILES * NCH)  // 1536

__device__ unsigned int g_counts[NCH * NBINS];   // zero-init at load; self-reset each run
__device__ unsigned int g_done;                  // self-wrapping via atomicInc

#define W_EDGE 0.20710678118654752f
#define W_DIAG 0.5f
#define W_CM1  (-0.91421356237309505f)   // W_CENT - 1

struct Row6 { float L, v0, v1, v2, v3, R; };

__device__ __forceinline__ Row6 load_row(const float* __restrict__ img,
                                         int y, int t, int lane) {
    Row6 r;
    if (y < IMG_H) {   // uniform per block -> shuffles safe
        const float4 v = *reinterpret_cast<const float4*>(img + (size_t)y * IMG_W + 4 * t);
        r.v0 = v.x; r.v1 = v.y; r.v2 = v.z; r.v3 = v.w;
        r.L = __shfl_up_sync(0xffffffffu, v.w, 1);
        r.R = __shfl_down_sync(0xffffffffu, v.x, 1);
        if (lane == 0)
            r.L = (t == 0) ? 0.0f : __ldg(img + (size_t)y * IMG_W + 4 * t - 1);
        if (lane == 31)
            r.R = (t == BLOCK - 1) ? 0.0f : __ldg(img + (size_t)y * IMG_W + 4 * t + 4);
    } else {
        r.L = r.v0 = r.v1 = r.v2 = r.v3 = r.R = 0.0f;
    }
    return r;
}

__global__ void __launch_bounds__(BLOCK)
lbp_hist_kernel(const float* __restrict__ x, float* __restrict__ out) {
    __shared__ unsigned int s_hist[NBINS];
    __shared__ unsigned int s_last;
    const int t    = threadIdx.x;
    const int lane = t & 31;
    const int ch   = blockIdx.y;
    const int y0   = blockIdx.x * ROWS;
    const float* __restrict__ img = x + (size_t)ch * IMG_H * IMG_W;

    if (t < NBINS) s_hist[t] = 0u;
    __syncthreads();

    // Two u32 accumulators, 4 x 8-bit fields each. p0: bins 0-3 (bit7=0),
    // p1: bins 4-7 (bit7=1). Field index within = 2*bit6 + bit5.
    unsigned int p0 = 0u, p1 = 0u;

    Row6 cur = load_row(img, y0, t, lane);

    #pragma unroll 4
    for (int r = 0; r < ROWS; ++r) {
        Row6 nxt = load_row(img, y0 + r + 1, t, lane);

        // s5 = nb5 - c, s7 = nb7 - c, with shared term tt = (C-1)*c + E*nc
        #define PX(a, c, e, na, nc, ne) do {                                   \
            float tt = fmaf(W_EDGE, (nc), W_CM1 * (c));                        \
            float s5 = fmaf(W_EDGE, (a), fmaf(W_DIAG, (na), tt));              \
            float s7 = fmaf(W_EDGE, (e), fmaf(W_DIAG, (ne), tt));              \
            unsigned int v = (s5 >= 0.0f) ? 0x100u : 1u;                       \
            v = ((nc) >= (c)) ? (v << 16) : v;                                 \
            if (s7 >= 0.0f) p1 += v; else p0 += v;                             \
        } while (0)

        PX(cur.L,  cur.v0, cur.v1, nxt.L,  nxt.v0, nxt.v1);
        PX(cur.v0, cur.v1, cur.v2, nxt.v0, nxt.v1, nxt.v2);
        PX(cur.v1, cur.v2, cur.v3, nxt.v1, nxt.v2, nxt.v3);
        PX(cur.v2, cur.v3, cur.R,  nxt.v2, nxt.v3, nxt.R);
        #undef PX

        cur = nxt;
    }

    // unpack + warp reduce + block accumulate
    #pragma unroll
    for (int b = 0; b < 4; ++b) {
        unsigned int c0 = (p0 >> (b * 8)) & 0xFFu;
        unsigned int c1 = (p1 >> (b * 8)) & 0xFFu;
        c0 = __reduce_add_sync(0xffffffffu, c0);
        c1 = __reduce_add_sync(0xffffffffu, c1);
        if (lane == 0) {
            atomicAdd(&s_hist[b], c0);
            atomicAdd(&s_hist[4 + b], c1);
        }
    }
    __syncthreads();
    if (t < NBINS) atomicAdd(&g_counts[ch * NBINS + t], s_hist[t]);
    __syncthreads();

    // Completion protocol: last block normalizes + resets counts for next replay.
    if (t == 0) {
        __threadfence();
        unsigned int old = atomicInc(&g_done, NBLOCKS - 1);  // wraps to 0 at NBLOCKS-1
        s_last = (old == NBLOCKS - 1) ? 1u : 0u;
    }
    __syncthreads();

    if (s_last) {
        __threadfence();
        for (int i = t; i < NCH * NBINS; i += BLOCK) {
            unsigned int c = atomicExch(&g_counts[i], 0u);   // read + self-reset
            out[i] = (float)c / 8355840.0f;                  // H*W * (255/8)
        }
    }
}

extern "C" void kernel_launch(void* const* d_in, const int* in_sizes, int n_in,
                              void* d_out, int out_size) {
    const float* x = (const float*)d_in[0];
    float* out = (float*)d_out;
    dim3 grid(TILES, NCH);
    lbp_hist_kernel<<<grid, BLOCK>>>(x, out);
}

// round 4
// speedup vs baseline: 1.1755x; 1.0873x over previous
#include <cuda_runtime.h>

// LocalBinaryLayer: LBP (radius=1, P=8) + 8-bin histogram (range 0..255, density).
// bin = code >> 5 == top 3 LBP bits (i=5,6,7) only:
//   i=5: (dy,dx)=(+s,-s)  bilinear over {(0,-1),(0,0),(1,-1),(1,0)}
//   i=6: (dy,dx)=(+1, 0)  exact neighbor (1,0)
//   i=7: (dy,dx)=(+s,+s)  bilinear over {(0,0),(0,1),(1,0),(1,1)}
// s = sqrt(2)/2, zero padding. Single kernel: per-block packed-register
// histograms -> global atomics -> last block normalizes & self-resets state.
//
// R4: ROWS 32->16 (grid 1536->3072 blocks) to fix warp starvation
// (occ was 58.5% with issue/occ ~0.93 => machine underfilled at 10.4 blk/SM).

#define IMG_W 512
#define IMG_H 512
#define NCH   96          // 32 batch * 3 channels
#define NBINS 8
#define BLOCK 128         // threads; each owns 4 columns -> 512 wide
#define ROWS  16          // rows per block tile (64 px/thread -> fits u8 fields)
#define TILES (IMG_H / ROWS)   // 32
#define NBLOCKS (TILES * NCH)  // 3072

__device__ unsigned int g_counts[NCH * NBINS];   // zero-init at load; self-reset each run
__device__ unsigned int g_done;                  // self-wrapping via atomicInc

#define W_EDGE 0.20710678118654752f
#define W_DIAG 0.5f
#define W_CM1  (-0.91421356237309505f)   // W_CENT - 1

struct Row6 { float L, v0, v1, v2, v3, R; };

__device__ __forceinline__ Row6 load_row(const float* __restrict__ img,
                                         int y, int t, int lane) {
    Row6 r;
    if (y < IMG_H) {   // uniform per block -> shuffles safe
        const float4 v = *reinterpret_cast<const float4*>(img + (size_t)y * IMG_W + 4 * t);
        r.v0 = v.x; r.v1 = v.y; r.v2 = v.z; r.v3 = v.w;
        r.L = __shfl_up_sync(0xffffffffu, v.w, 1);
        r.R = __shfl_down_sync(0xffffffffu, v.x, 1);
        if (lane == 0)
            r.L = (t == 0) ? 0.0f : __ldg(img + (size_t)y * IMG_W + 4 * t - 1);
        if (lane == 31)
            r.R = (t == BLOCK - 1) ? 0.0f : __ldg(img + (size_t)y * IMG_W + 4 * t + 4);
    } else {
        r.L = r.v0 = r.v1 = r.v2 = r.v3 = r.R = 0.0f;
    }
    return r;
}

__global__ void __launch_bounds__(BLOCK, 16)
lbp_hist_kernel(const float* __restrict__ x, float* __restrict__ out) {
    __shared__ unsigned int s_hist[NBINS];
    __shared__ unsigned int s_last;
    const int t    = threadIdx.x;
    const int lane = t & 31;
    const int ch   = blockIdx.y;
    const int y0   = blockIdx.x * ROWS;
    const float* __restrict__ img = x + (size_t)ch * IMG_H * IMG_W;

    if (t < NBINS) s_hist[t] = 0u;
    __syncthreads();

    // Two u32 accumulators, 4 x 8-bit fields each. p0: bins 0-3 (bit7=0),
    // p1: bins 4-7 (bit7=1). Field index within = 2*bit6 + bit5.
    unsigned int p0 = 0u, p1 = 0u;

    Row6 cur = load_row(img, y0, t, lane);

    #pragma unroll 4
    for (int r = 0; r < ROWS; ++r) {
        Row6 nxt = load_row(img, y0 + r + 1, t, lane);

        // s5 = nb5 - c, s7 = nb7 - c, with shared term tt = (C-1)*c + E*nc
        #define PX(a, c, e, na, nc, ne) do {                                   \
            float tt = fmaf(W_EDGE, (nc), W_CM1 * (c));                        \
            float s5 = fmaf(W_EDGE, (a), fmaf(W_DIAG, (na), tt));              \
            float s7 = fmaf(W_EDGE, (e), fmaf(W_DIAG, (ne), tt));              \
            unsigned int v = (s5 >= 0.0f) ? 0x100u : 1u;                       \
            v = ((nc) >= (c)) ? (v << 16) : v;                                 \
            if (s7 >= 0.0f) p1 += v; else p0 += v;                             \
        } while (0)

        PX(cur.L,  cur.v0, cur.v1, nxt.L,  nxt.v0, nxt.v1);
        PX(cur.v0, cur.v1, cur.v2, nxt.v0, nxt.v1, nxt.v2);
        PX(cur.v1, cur.v2, cur.v3, nxt.v1, nxt.v2, nxt.v3);
        PX(cur.v2, cur.v3, cur.R,  nxt.v2, nxt.v3, nxt.R);
        #undef PX

        cur = nxt;
    }

    // unpack + warp reduce + block accumulate
    #pragma unroll
    for (int b = 0; b < 4; ++b) {
        unsigned int c0 = (p0 >> (b * 8)) & 0xFFu;
        unsigned int c1 = (p1 >> (b * 8)) & 0xFFu;
        c0 = __reduce_add_sync(0xffffffffu, c0);
        c1 = __reduce_add_sync(0xffffffffu, c1);
        if (lane == 0) {
            atomicAdd(&s_hist[b], c0);
            atomicAdd(&s_hist[4 + b], c1);
        }
    }
    __syncthreads();
    if (t < NBINS) atomicAdd(&g_counts[ch * NBINS + t], s_hist[t]);
    __syncthreads();

    // Completion protocol: last block normalizes + resets counts for next replay.
    if (t == 0) {
        __threadfence();
        unsigned int old = atomicInc(&g_done, NBLOCKS - 1);  // wraps to 0 at NBLOCKS-1
        s_last = (old == NBLOCKS - 1) ? 1u : 0u;
    }
    __syncthreads();

    if (s_last) {
        __threadfence();
        for (int i = t; i < NCH * NBINS; i += BLOCK) {
            unsigned int c = atomicExch(&g_counts[i], 0u);   // read + self-reset
            out[i] = (float)c / 8355840.0f;                  // H*W * (255/8)
        }
    }
}

extern "C" void kernel_launch(void* const* d_in, const int* in_sizes, int n_in,
                              void* d_out, int out_size) {
    const float* x = (const float*)d_in[0];
    float* out = (float*)d_out;
    dim3 grid(TILES, NCH);
    lbp_hist_kernel<<<grid, BLOCK>>>(x, out);
}

// round 5
// speedup vs baseline: 1.2247x; 1.0419x over previous
#include <cuda_runtime.h>

// LocalBinaryLayer: LBP (radius=1, P=8) + 8-bin histogram (range 0..255, density).
// bin = code >> 5 == top 3 LBP bits (i=5,6,7) only:
//   i=5: (dy,dx)=(+s,-s)  bilinear over {(0,-1),(0,0),(1,-1),(1,0)}
//   i=6: (dy,dx)=(+1, 0)  exact neighbor (1,0)
//   i=7: (dy,dx)=(+s,+s)  bilinear over {(0,0),(0,1),(1,0),(1,1)}
// s = sqrt(2)/2, zero padding. Single kernel: per-block packed-register
// histograms -> global atomics -> last block normalizes & self-resets state.
//
// R4: ROWS 32->16 (grid 1536->3072 blocks) to fix warp starvation
// (occ was 58.5% with issue/occ ~0.93 => machine underfilled at 10.4 blk/SM).

#define IMG_W 512
#define IMG_H 512
#define NCH   96          // 32 batch * 3 channels
#define NBINS 8
#define BLOCK 128         // threads; each owns 4 columns -> 512 wide
#define ROWS  16          // rows per block tile (64 px/thread -> fits u8 fields)
#define TILES (IMG_H / ROWS)   // 32
#define NBLOCKS (TILES * NCH)  // 3072

__device__ unsigned int g_counts[NCH * NBINS];   // zero-init at load; self-reset each run
__device__ unsigned int g_done;                  // self-wrapping via atomicInc

#define W_EDGE 0.20710678118654752f
#define W_DIAG 0.5f
#define W_CM1  (-0.91421356237309505f)   // W_CENT - 1

struct Row6 { float L, v0, v1, v2, v3, R; };

__device__ __forceinline__ Row6 load_row(const float* __restrict__ img,
                                         int y, int t, int lane) {
    Row6 r;
    if (y < IMG_H) {   // uniform per block -> shuffles safe
        const float4 v = *reinterpret_cast<const float4*>(img + (size_t)y * IMG_W + 4 * t);
        r.v0 = v.x; r.v1 = v.y; r.v2 = v.z; r.v3 = v.w;
        r.L = __shfl_up_sync(0xffffffffu, v.w, 1);
        r.R = __shfl_down_sync(0xffffffffu, v.x, 1);
        if (lane == 0)
            r.L = (t == 0) ? 0.0f : __ldg(img + (size_t)y * IMG_W + 4 * t - 1);
        if (lane == 31)
            r.R = (t == BLOCK - 1) ? 0.0f : __ldg(img + (size_t)y * IMG_W + 4 * t + 4);
    } else {
        r.L = r.v0 = r.v1 = r.v2 = r.v3 = r.R = 0.0f;
    }
    return r;
}

__global__ void __launch_bounds__(BLOCK, 16)
lbp_hist_kernel(const float* __restrict__ x, float* __restrict__ out) {
    __shared__ unsigned int s_hist[NBINS];
    __shared__ unsigned int s_last;
    const int t    = threadIdx.x;
    const int lane = t & 31;
    const int ch   = blockIdx.y;
    const int y0   = blockIdx.x * ROWS;
    const float* __restrict__ img = x + (size_t)ch * IMG_H * IMG_W;

    if (t < NBINS) s_hist[t] = 0u;
    __syncthreads();

    // Two u32 accumulators, 4 x 8-bit fields each. p0: bins 0-3 (bit7=0),
    // p1: bins 4-7 (bit7=1). Field index within = 2*bit6 + bit5.
    unsigned int p0 = 0u, p1 = 0u;

    Row6 cur = load_row(img, y0, t, lane);

    #pragma unroll 4
    for (int r = 0; r < ROWS; ++r) {
        Row6 nxt = load_row(img, y0 + r + 1, t, lane);

        // s5 = nb5 - c, s7 = nb7 - c, with shared term tt = (C-1)*c + E*nc
        #define PX(a, c, e, na, nc, ne) do {                                   \
            float tt = fmaf(W_EDGE, (nc), W_CM1 * (c));                        \
            float s5 = fmaf(W_EDGE, (a), fmaf(W_DIAG, (na), tt));              \
            float s7 = fmaf(W_EDGE, (e), fmaf(W_DIAG, (ne), tt));              \
            unsigned int v = (s5 >= 0.0f) ? 0x100u : 1u;                       \
            v = ((nc) >= (c)) ? (v << 16) : v;                                 \
            if (s7 >= 0.0f) p1 += v; else p0 += v;                             \
        } while (0)

        PX(cur.L,  cur.v0, cur.v1, nxt.L,  nxt.v0, nxt.v1);
        PX(cur.v0, cur.v1, cur.v2, nxt.v0, nxt.v1, nxt.v2);
        PX(cur.v1, cur.v2, cur.v3, nxt.v1, nxt.v2, nxt.v3);
        PX(cur.v2, cur.v3, cur.R,  nxt.v2, nxt.v3, nxt.R);
        #undef PX

        cur = nxt;
    }

    // unpack + warp reduce + block accumulate
    #pragma unroll
    for (int b = 0; b < 4; ++b) {
        unsigned int c0 = (p0 >> (b * 8)) & 0xFFu;
        unsigned int c1 = (p1 >> (b * 8)) & 0xFFu;
        c0 = __reduce_add_sync(0xffffffffu, c0);
        c1 = __reduce_add_sync(0xffffffffu, c1);
        if (lane == 0) {
            atomicAdd(&s_hist[b], c0);
            atomicAdd(&s_hist[4 + b], c1);
        }
    }
    __syncthreads();
    if (t < NBINS) atomicAdd(&g_counts[ch * NBINS + t], s_hist[t]);
    __syncthreads();

    // Completion protocol: last block normalizes + resets counts for next replay.
    if (t == 0) {
        __threadfence();
        unsigned int old = atomicInc(&g_done, NBLOCKS - 1);  // wraps to 0 at NBLOCKS-1
        s_last = (old == NBLOCKS - 1) ? 1u : 0u;
    }
    __syncthreads();

    if (s_last) {
        __threadfence();
        for (int i = t; i < NCH * NBINS; i += BLOCK) {
            unsigned int c = atomicExch(&g_counts[i], 0u);   // read + self-reset
            out[i] = (float)c / 8355840.0f;                  // H*W * (255/8)
        }
    }
}

extern "C" void kernel_launch(void* const* d_in, const int* in_sizes, int n_in,
                              void* d_out, int out_size) {
    const float* x = (const float*)d_in[0];
    float* out = (float*)d_out;
    dim3 grid(TILES, NCH);
    lbp_hist_kernel<<<grid, BLOCK>>>(x, out);
}

// round 6
// speedup vs baseline: 1.2315x; 1.0055x over previous
#include <cuda_runtime.h>

// LocalBinaryLayer: LBP (radius=1, P=8) + 8-bin histogram (range 0..255, density).
// bin = code >> 5 == top 3 LBP bits (i=5,6,7) only:
//   i=5: (dy,dx)=(+s,-s)  bilinear over {(0,-1),(0,0),(1,-1),(1,0)}
//   i=6: (dy,dx)=(+1, 0)  exact neighbor (1,0)
//   i=7: (dy,dx)=(+s,+s)  bilinear over {(0,0),(0,1),(1,0),(1,1)}
// s = sqrt(2)/2, zero padding. Single kernel: per-block packed-register
// histograms -> global atomics -> last block normalizes & self-resets state.
//
// R4: ROWS 32->16 (grid 1536->3072 blocks) to fix warp starvation
// (occ was 58.5% with issue/occ ~0.93 => machine underfilled at 10.4 blk/SM).

#define IMG_W 512
#define IMG_H 512
#define NCH   96          // 32 batch * 3 channels
#define NBINS 8
#define BLOCK 128         // threads; each owns 4 columns -> 512 wide
#define ROWS  16          // rows per block tile (64 px/thread -> fits u8 fields)
#define TILES (IMG_H / ROWS)   // 32
#define NBLOCKS (TILES * NCH)  // 3072

__device__ unsigned int g_counts[NCH * NBINS];   // zero-init at load; self-reset each run
__device__ unsigned int g_done;                  // self-wrapping via atomicInc

#define W_EDGE 0.20710678118654752f
#define W_DIAG 0.5f
#define W_CM1  (-0.91421356237309505f)   // W_CENT - 1

struct Row6 { float L, v0, v1, v2, v3, R; };

__device__ __forceinline__ Row6 load_row(const float* __restrict__ img,
                                         int y, int t, int lane) {
    Row6 r;
    if (y < IMG_H) {   // uniform per block -> shuffles safe
        const float4 v = *reinterpret_cast<const float4*>(img + (size_t)y * IMG_W + 4 * t);
        r.v0 = v.x; r.v1 = v.y; r.v2 = v.z; r.v3 = v.w;
        r.L = __shfl_up_sync(0xffffffffu, v.w, 1);
        r.R = __shfl_down_sync(0xffffffffu, v.x, 1);
        if (lane == 0)
            r.L = (t == 0) ? 0.0f : __ldg(img + (size_t)y * IMG_W + 4 * t - 1);
        if (lane == 31)
            r.R = (t == BLOCK - 1) ? 0.0f : __ldg(img + (size_t)y * IMG_W + 4 * t + 4);
    } else {
        r.L = r.v0 = r.v1 = r.v2 = r.v3 = r.R = 0.0f;
    }
    return r;
}

__global__ void __launch_bounds__(BLOCK, 16)
lbp_hist_kernel(const float* __restrict__ x, float* __restrict__ out) {
    __shared__ unsigned int s_hist[NBINS];
    __shared__ unsigned int s_last;
    const int t    = threadIdx.x;
    const int lane = t & 31;
    const int ch   = blockIdx.y;
    const int y0   = blockIdx.x * ROWS;
    const float* __restrict__ img = x + (size_t)ch * IMG_H * IMG_W;

    if (t < NBINS) s_hist[t] = 0u;
    __syncthreads();

    // Two u32 accumulators, 4 x 8-bit fields each. p0: bins 0-3 (bit7=0),
    // p1: bins 4-7 (bit7=1). Field index within = 2*bit6 + bit5.
    unsigned int p0 = 0u, p1 = 0u;

    Row6 cur = load_row(img, y0, t, lane);

    #pragma unroll 4
    for (int r = 0; r < ROWS; ++r) {
        Row6 nxt = load_row(img, y0 + r + 1, t, lane);

        // s5 = nb5 - c, s7 = nb7 - c, with shared term tt = (C-1)*c + E*nc
        #define PX(a, c, e, na, nc, ne) do {                                   \
            float tt = fmaf(W_EDGE, (nc), W_CM1 * (c));                        \
            float s5 = fmaf(W_EDGE, (a), fmaf(W_DIAG, (na), tt));              \
            float s7 = fmaf(W_EDGE, (e), fmaf(W_DIAG, (ne), tt));              \
            unsigned int v = (s5 >= 0.0f) ? 0x100u : 1u;                       \
            v = ((nc) >= (c)) ? (v << 16) : v;                                 \
            if (s7 >= 0.0f) p1 += v; else p0 += v;                             \
        } while (0)

        PX(cur.L,  cur.v0, cur.v1, nxt.L,  nxt.v0, nxt.v1);
        PX(cur.v0, cur.v1, cur.v2, nxt.v0, nxt.v1, nxt.v2);
        PX(cur.v1, cur.v2, cur.v3, nxt.v1, nxt.v2, nxt.v3);
        PX(cur.v2, cur.v3, cur.R,  nxt.v2, nxt.v3, nxt.R);
        #undef PX

        cur = nxt;
    }

    // unpack + warp reduce + block accumulate
    #pragma unroll
    for (int b = 0; b < 4; ++b) {
        unsigned int c0 = (p0 >> (b * 8)) & 0xFFu;
        unsigned int c1 = (p1 >> (b * 8)) & 0xFFu;
        c0 = __reduce_add_sync(0xffffffffu, c0);
        c1 = __reduce_add_sync(0xffffffffu, c1);
        if (lane == 0) {
            atomicAdd(&s_hist[b], c0);
            atomicAdd(&s_hist[4 + b], c1);
        }
    }
    __syncthreads();
    if (t < NBINS) atomicAdd(&g_counts[ch * NBINS + t], s_hist[t]);
    __syncthreads();

    // Completion protocol: last block normalizes + resets counts for next replay.
    if (t == 0) {
        __threadfence();
        unsigned int old = atomicInc(&g_done, NBLOCKS - 1);  // wraps to 0 at NBLOCKS-1
        s_last = (old == NBLOCKS - 1) ? 1u : 0u;
    }
    __syncthreads();

    if (s_last) {
        __threadfence();
        for (int i = t; i < NCH * NBINS; i += BLOCK) {
            unsigned int c = atomicExch(&g_counts[i], 0u);   // read + self-reset
            out[i] = (float)c / 8355840.0f;                  // H*W * (255/8)
        }
    }
}

extern "C" void kernel_launch(void* const* d_in, const int* in_sizes, int n_in,
                              void* d_out, int out_size) {
    const float* x = (const float*)d_in[0];
    float* out = (float*)d_out;
    dim3 grid(TILES, NCH);
    lbp_hist_kernel<<<grid, BLOCK>>>(x, out);
}